// round 5
// baseline (speedup 1.0000x reference)
#include <cuda_runtime.h>
#include <cuda_bf16.h>

#define T_MAX 11
#define UNROLL 4          // float4 outputs per thread
#define BLK   256

// ---------------------------------------------------------------------------
// Single fused kernel.
// Grid: (GX, S). Block: 256 threads. per_block = UNROLL*BLK float4 of new_bert.
// Every block recomputes its segment's softmax weights (L2-hot, cheap), then
// streams its chunk with 4-wide load-level parallelism.
// Block (0, s) additionally handles new_mtl row s and probs row s.
// ---------------------------------------------------------------------------
__global__ void __launch_bounds__(BLK)
k_fused(const float* __restrict__ bert,
        const float* __restrict__ hist,
        const float* __restrict__ mtl,
        const float* __restrict__ Wv,
        const float* __restrict__ bv,
        const int*   __restrict__ slice_mask,
        float* __restrict__ out_bert,
        float* __restrict__ out_mtl,
        float* __restrict__ out_probs,
        int hidden, int n4_bert, int n4_mtl, int S)
{
    __shared__ int   s_mask[64];
    __shared__ float s_e[T_MAX + 5];
    __shared__ float s_w[T_MAX + 5];

    const int tid  = threadIdx.x;
    const int lane = tid & 31;
    const int warp = tid >> 5;
    const int s    = blockIdx.y;

    // ---- segment geometry ----
    if (tid < S) s_mask[tid] = slice_mask[tid];
    __syncthreads();
    int off = 0;
    #pragma unroll 4
    for (int t = 0; t < s; t++) off += s_mask[t];
    const int cnt = s_mask[s];

    // ---- per-segment logits: warp r handles row off+r (cnt <= 11) ----
    const int nv4 = hidden >> 2;
    for (int r = warp; r < cnt; r += 8) {
        const float4* hr = (const float4*)(hist + (size_t)(off + r) * hidden);
        const float4* wv = (const float4*)Wv;
        float acc = 0.f;
        for (int c = lane; c < nv4; c += 32) {
            float4 h = __ldg(hr + c);
            float4 w = __ldg(wv + c);
            acc = fmaf(h.x, w.x, acc);
            acc = fmaf(h.y, w.y, acc);
            acc = fmaf(h.z, w.z, acc);
            acc = fmaf(h.w, w.w, acc);
        }
        #pragma unroll
        for (int o = 16; o; o >>= 1)
            acc += __shfl_down_sync(0xffffffffu, acc, o);
        if (lane == 0) s_e[r] = __expf(acc + bv[0]);
    }
    __syncthreads();

    if (tid < cnt) {
        float sum = 0.f;
        for (int j = 0; j < cnt; j++) sum += s_e[j];
        s_w[tid] = s_e[tid] * (1.f / sum);
    }
    __syncthreads();

    // ---- main stream: UNROLL outputs per thread, j-outer for 4-wide MLP ----
    const int e0 = blockIdx.x * (UNROLL * BLK) + tid;
    const float4* bbase = (const float4*)bert + (size_t)off * n4_bert;
    float4* obase = (float4*)out_bert + (size_t)s * n4_bert;

    if (e0 + (UNROLL - 1) * BLK < n4_bert) {
        // fast path: all 4 in range
        float4 acc[UNROLL];
        #pragma unroll
        for (int u = 0; u < UNROLL; u++) acc[u] = make_float4(0.f, 0.f, 0.f, 0.f);

        for (int j = 0; j < cnt; j++) {
            const float  w = s_w[j];
            const float4* p = bbase + (size_t)j * n4_bert + e0;
            float4 v[UNROLL];
            #pragma unroll
            for (int u = 0; u < UNROLL; u++) v[u] = __ldg(p + u * BLK);
            #pragma unroll
            for (int u = 0; u < UNROLL; u++) {
                acc[u].x = fmaf(w, v[u].x, acc[u].x);
                acc[u].y = fmaf(w, v[u].y, acc[u].y);
                acc[u].z = fmaf(w, v[u].z, acc[u].z);
                acc[u].w = fmaf(w, v[u].w, acc[u].w);
            }
        }
        #pragma unroll
        for (int u = 0; u < UNROLL; u++) obase[e0 + u * BLK] = acc[u];
    } else {
        // tail path
        for (int u = 0; u < UNROLL; u++) {
            int e = e0 + u * BLK;
            if (e >= n4_bert) break;
            float4 acc = make_float4(0.f, 0.f, 0.f, 0.f);
            const float4* p = bbase + e;
            for (int j = 0; j < cnt; j++) {
                float  w = s_w[j];
                float4 v = __ldg(p + (size_t)j * n4_bert);
                acc.x = fmaf(w, v.x, acc.x);
                acc.y = fmaf(w, v.y, acc.y);
                acc.z = fmaf(w, v.z, acc.z);
                acc.w = fmaf(w, v.w, acc.w);
            }
            obase[e] = acc;
        }
    }

    // ---- block (0, s): new_mtl row + probs row ----
    if (blockIdx.x == 0) {
        if (tid < n4_mtl) {
            const float4* p = (const float4*)mtl + (size_t)off * n4_mtl + tid;
            float4 acc = make_float4(0.f, 0.f, 0.f, 0.f);
            for (int j = 0; j < cnt; j++) {
                float  w = s_w[j];
                float4 v = __ldg(p + (size_t)j * n4_mtl);
                acc.x = fmaf(w, v.x, acc.x);
                acc.y = fmaf(w, v.y, acc.y);
                acc.z = fmaf(w, v.z, acc.z);
                acc.w = fmaf(w, v.w, acc.w);
            }
            ((float4*)out_mtl)[(size_t)s * n4_mtl + tid] = acc;
        }
        if (tid < T_MAX) {
            int padl = T_MAX - cnt;
            out_probs[s * T_MAX + tid] = (tid >= padl) ? s_w[tid - padl] : 0.f;
        }
    }
}

// ---------------------------------------------------------------------------
// Launch. Inputs (metadata order):
//   0: bert_representation (rows, seq, hidden) f32
//   1: history_attention_input (rows, hidden)  f32
//   2: mtl_input (rows, hidden)                f32
//   3: W (1, hidden) f32     4: b (1,) f32
//   5: slice_mask (rows,) i32   6: slice_num i32 (S derived from out_size)
// Output: [new_bert (S,seq,hidden) | new_mtl (S,hidden) | probs (S,T_MAX)] f32
// ---------------------------------------------------------------------------
extern "C" void kernel_launch(void* const* d_in, const int* in_sizes, int n_in,
                              void* d_out, int out_size)
{
    const float* bert = (const float*)d_in[0];
    const float* hist = (const float*)d_in[1];
    const float* mtl  = (const float*)d_in[2];
    const float* Wv   = (const float*)d_in[3];
    const float* bv   = (const float*)d_in[4];
    const int*   sm   = (const int*)d_in[5];

    const int hidden = in_sizes[3];                   // 768
    const int rows   = in_sizes[1] / hidden;          // 64
    const int seq    = in_sizes[0] / (rows * hidden); // 512
    const int S      = out_size / (seq * hidden + hidden + T_MAX); // 16

    float* out_bert  = (float*)d_out;
    float* out_mtl   = out_bert + (size_t)S * seq * hidden;
    float* out_probs = out_mtl  + (size_t)S * hidden;

    const int n4_bert = seq * hidden / 4;   // 98304
    const int n4_mtl  = hidden / 4;         // 192

    const int per_block = UNROLL * BLK;     // 1024 float4
    int GX = (n4_bert + per_block - 1) / per_block;   // 96

    dim3 grid(GX, S);                       // 1536 blocks
    k_fused<<<grid, BLK>>>(bert, hist, mtl, Wv, bv, sm,
                           out_bert, out_mtl, out_probs,
                           hidden, n4_bert, n4_mtl, S);
}